// round 8
// baseline (speedup 1.0000x reference)
#include <cuda_runtime.h>
#include <cuda_fp16.h>
#include <cstdint>
#include <cstddef>

#define UNITS 512
#define VOCAB 32000
#define BATCH 128
#define SEQ   64

// ---------------- scratch (no allocation allowed) ----------------
__device__ float g_score[BATCH * SEQ];
__device__ float g_xc[BATCH * 2 * UNITS];        // [x (emb) | context]
__device__ float g_preact[BATCH * 3 * UNITS];    // xc @ gru_k + gru_b[0]
__device__ float g_y[BATCH * UNITS];             // relu(state @ dW + db)

// pre-split weights, transposed to [n][kpair] packed fp16x2 (small mats only)
__device__ uint32_t g_W0t    [512  * 256];
__device__ uint32_t g_grukt_h[1536 * 512];
__device__ uint32_t g_grukt_l[1536 * 512];
__device__ uint32_t g_dWt_h  [512  * 256];
__device__ uint32_t g_dWt_l  [512  * 256];

// ---------------- helpers ----------------
__device__ __forceinline__ uint32_t packh(__half a, __half b) {
    return (uint32_t)__half_as_ushort(a) | ((uint32_t)__half_as_ushort(b) << 16);
}

__device__ __forceinline__ void splith(float v0, float v1, uint32_t& hi, uint32_t& lo) {
    __half h0 = __float2half_rn(v0), h1 = __float2half_rn(v1);
    __half l0 = __float2half_rn(v0 - __half2float(h0));
    __half l1 = __float2half_rn(v1 - __half2float(h1));
    hi = packh(h0, h1);
    lo = packh(l0, l1);
}

__device__ __forceinline__ void mma16(float c[4], const uint32_t a[4],
                                      uint32_t b0, uint32_t b1) {
    asm volatile(
        "mma.sync.aligned.m16n8k16.row.col.f32.f16.f16.f32 "
        "{%0,%1,%2,%3}, {%4,%5,%6,%7}, {%8,%9}, {%0,%1,%2,%3};"
        : "+f"(c[0]), "+f"(c[1]), "+f"(c[2]), "+f"(c[3])
        : "r"(a[0]), "r"(a[1]), "r"(a[2]), "r"(a[3]), "r"(b0), "r"(b1));
}

// ---------------- weight transpose + fp16-split conversion ----------------
// W: [K, N] fp32 row-major  ->  oh/ol: [N, K/2] packed fp16x2 (kpair-major)
__global__ void __launch_bounds__(256) k_conv(const float* __restrict__ W,
                                              uint32_t* __restrict__ oh,
                                              uint32_t* __restrict__ ol,
                                              int K, int N) {
    __shared__ float s[64][65];
    const int tid = threadIdx.x;
    const int n0 = blockIdx.x * 64, k0 = blockIdx.y * 64;
    for (int i = tid; i < 64 * 64; i += 256) {
        int r = i >> 6, c = i & 63;
        s[r][c] = W[(size_t)(k0 + r) * N + n0 + c];
    }
    __syncthreads();
    const int Kp = K >> 1;
    for (int i = tid; i < 64 * 32; i += 256) {
        int n = i >> 5, kp = i & 31;
        float v0 = s[2 * kp][n], v1 = s[2 * kp + 1][n];
        __half h0 = __float2half_rn(v0), h1 = __float2half_rn(v1);
        size_t o = (size_t)(n0 + n) * Kp + (k0 >> 1) + kp;
        oh[o] = packh(h0, h1);
        if (ol) {
            __half l0 = __float2half_rn(v0 - __half2float(h0));
            __half l1 = __float2half_rn(v1 - __half2float(h1));
            ol[o] = packh(l0, l1);
        }
    }
}

// ---------------- fp16 GEMM core (pre-split B) ----------------
// acc += A(M_BLK x K fp32) @ B(K x N_BLK, pre-split fp16 kpair-packed)
// PASSES=1: Ah*Bh          (err ~ A+B quant, ~2^-11 each)
// PASSES=3: + Al*Bh + Ah*Bl (err ~ 2^-21)
template <int M_BLK, int N_BLK, int NTHR, int WM, int WN, int MT, int NT, int PASSES>
__device__ __forceinline__ void gemm_f16(const float* __restrict__ A, int lda,
                                         const uint32_t* __restrict__ Bh,
                                         const uint32_t* __restrict__ Bl, int ldb_kp,
                                         int K, float acc[MT][NT][4], uint32_t* sm32) {
    constexpr int P = 20;      // 16 kpairs + 4 pad
    constexpr bool MP = (PASSES >= 3);
    uint32_t* sAh = sm32;
    uint32_t* sAl = sAh + M_BLK * P;
    uint32_t* sBh = sAl + (MP ? M_BLK * P : 0);
    uint32_t* sBl = sBh + N_BLK * P;

    const int tid = threadIdx.x, lane = tid & 31, warp = tid >> 5;
    const int wm = warp / WN, wn = warp % WN;
    const int grp = lane >> 2, qid = lane & 3;

    for (int k0 = 0; k0 < K; k0 += 32) {
        for (int i = tid; i < M_BLK * 16; i += NTHR) {
            int r = i >> 4, kp = i & 15;
            float2 v = *(const float2*)&A[(size_t)r * lda + k0 + kp * 2];
            if (MP) {
                uint32_t hi, lo; splith(v.x, v.y, hi, lo);
                sAh[r * P + kp] = hi;
                sAl[r * P + kp] = lo;
            } else {
                sAh[r * P + kp] = packh(__float2half_rn(v.x), __float2half_rn(v.y));
            }
        }
        for (int i = tid * 4; i < N_BLK * 16; i += NTHR * 4) {
            int n = i >> 4, kp = i & 15;
            size_t src = (size_t)n * ldb_kp + (k0 >> 1) + kp;
            *(uint4*)&sBh[n * P + kp] = *(const uint4*)&Bh[src];
            if (MP)
                *(uint4*)&sBl[n * P + kp] = *(const uint4*)&Bl[src];
        }
        __syncthreads();

        #pragma unroll
        for (int kk = 0; kk < 2; kk++) {
            const int kp0 = kk * 8 + qid;
            uint32_t ah[MT][4], al[MT][4];
            #pragma unroll
            for (int mt = 0; mt < MT; mt++) {
                int r = (wm * MT + mt) * 16 + grp;
                ah[mt][0] = sAh[r * P + kp0];
                ah[mt][1] = sAh[(r + 8) * P + kp0];
                ah[mt][2] = sAh[r * P + kp0 + 4];
                ah[mt][3] = sAh[(r + 8) * P + kp0 + 4];
                if (MP) {
                    al[mt][0] = sAl[r * P + kp0];
                    al[mt][1] = sAl[(r + 8) * P + kp0];
                    al[mt][2] = sAl[r * P + kp0 + 4];
                    al[mt][3] = sAl[(r + 8) * P + kp0 + 4];
                }
            }
            #pragma unroll
            for (int nt = 0; nt < NT; nt++) {
                int n = (wn * NT + nt) * 8 + grp;
                uint32_t bh0 = sBh[n * P + kp0], bh1 = sBh[n * P + kp0 + 4];
                #pragma unroll
                for (int mt = 0; mt < MT; mt++)
                    mma16(acc[mt][nt], ah[mt], bh0, bh1);
                if (MP) {
                    uint32_t bl0 = sBl[n * P + kp0], bl1 = sBl[n * P + kp0 + 4];
                    #pragma unroll
                    for (int mt = 0; mt < MT; mt++) {
                        mma16(acc[mt][nt], al[mt], bh0, bh1);
                        mma16(acc[mt][nt], ah[mt], bl0, bl1);
                    }
                }
            }
        }
        __syncthreads();
    }
}

// ---------------- kernel 1: fused attention-score GEMM (1-pass) ----------------
__global__ void __launch_bounds__(512) k_score(const float* __restrict__ attn,
                                               const float* __restrict__ b0,
                                               const float* __restrict__ b1,
                                               const float* __restrict__ vW) {
    extern __shared__ uint32_t sm32[];
    constexpr int M_BLK = 64, N_BLK = 128, NTHR = 512, WM = 2, WN = 8, MT = 2, NT = 2;
    constexpr int GEMM_W = M_BLK * 20 + N_BLK * 20;
    float* sScore = (float*)(sm32 + GEMM_W);

    const int b = blockIdx.x;
    const int tid = threadIdx.x, lane = tid & 31, warp = tid >> 5;
    const int wm = warp / WN, wn = warp % WN;
    const int grp = lane >> 2, qid = lane & 3;

    if (tid < SEQ) sScore[tid] = 0.f;

    float rs[MT][2] = {};
    for (int nc = 0; nc < UNITS / N_BLK; nc++) {
        float acc[MT][NT][4] = {};
        gemm_f16<M_BLK, N_BLK, NTHR, WM, WN, MT, NT, 1>(
            attn + (size_t)b * SEQ * UNITS, UNITS,
            g_W0t + (size_t)nc * N_BLK * 256, nullptr, 256, UNITS, acc, sm32);

        #pragma unroll
        for (int mt = 0; mt < MT; mt++) {
            #pragma unroll
            for (int nt = 0; nt < NT; nt++) {
                int c0 = nc * N_BLK + (wn * NT + nt) * 8 + qid * 2;
                float bia0 = __ldg(&b0[c0]) + __ldg(&b1[c0]);
                float bia1 = __ldg(&b0[c0 + 1]) + __ldg(&b1[c0 + 1]);
                float v0 = __ldg(&vW[c0]), v1 = __ldg(&vW[c0 + 1]);
                rs[mt][0] += tanhf(acc[mt][nt][0] + bia0) * v0 + tanhf(acc[mt][nt][1] + bia1) * v1;
                rs[mt][1] += tanhf(acc[mt][nt][2] + bia0) * v0 + tanhf(acc[mt][nt][3] + bia1) * v1;
            }
        }
    }
    #pragma unroll
    for (int mt = 0; mt < MT; mt++) {
        #pragma unroll
        for (int h = 0; h < 2; h++) {
            float v = rs[mt][h];
            v += __shfl_xor_sync(0xffffffffu, v, 1);
            v += __shfl_xor_sync(0xffffffffu, v, 2);
            if (qid == 0) {
                int r = (wm * MT + mt) * 16 + h * 8 + grp;
                atomicAdd(&sScore[r], v);
            }
        }
    }
    __syncthreads();
    if (tid < SEQ) g_score[b * SEQ + tid] = sScore[tid];
}

// ---------------- kernel 2: softmax + context + embedding gather ------
__global__ void __launch_bounds__(256) k_softmax_ctx(const float* __restrict__ attn,
                                                     const int* __restrict__ inputs,
                                                     const float* __restrict__ emb,
                                                     float* __restrict__ alpha_out) {
    __shared__ float sA[SEQ];
    __shared__ float sRed;
    const int b = blockIdx.x, tid = threadIdx.x;

    if (tid < SEQ) sA[tid] = g_score[b * SEQ + tid];
    __syncthreads();
    if (tid == 0) {
        float m = sA[0];
        for (int i = 1; i < SEQ; i++) m = fmaxf(m, sA[i]);
        sRed = m;
    }
    __syncthreads();
    if (tid < SEQ) sA[tid] = expf(sA[tid] - sRed);
    __syncthreads();
    if (tid == 0) {
        float s = 0.f;
        for (int i = 0; i < SEQ; i++) s += sA[i];
        sRed = s;
    }
    __syncthreads();
    if (tid < SEQ) {
        sA[tid] = sA[tid] / sRed;
        alpha_out[b * SEQ + tid] = sA[tid];
    }
    __syncthreads();

    const int idx = inputs[b];
    for (int u = tid; u < UNITS; u += 256) {
        float accv = 0.f;
        const float* ap = attn + (size_t)b * SEQ * UNITS + u;
        #pragma unroll 8
        for (int s = 0; s < SEQ; s++) accv += sA[s] * ap[s * UNITS];
        g_xc[b * 2 * UNITS + UNITS + u] = accv;                     // context
        g_xc[b * 2 * UNITS + u] = emb[(size_t)idx * UNITS + u];     // emb gather
    }
}

// ---------------- kernel 3: GRU input GEMM (3-pass) ----------------
__global__ void __launch_bounds__(256) k_gru(const float* __restrict__ gru_b) {
    extern __shared__ uint32_t sm32[];
    constexpr int M_BLK = 64, N_BLK = 64, NTHR = 256, WM = 2, WN = 4, MT = 2, NT = 2;
    const int n0 = blockIdx.x * N_BLK;
    const int m0 = blockIdx.y * M_BLK;

    float acc[MT][NT][4] = {};
    gemm_f16<M_BLK, N_BLK, NTHR, WM, WN, MT, NT, 3>(
        g_xc + (size_t)m0 * 2 * UNITS, 2 * UNITS,
        g_grukt_h + (size_t)n0 * 512, g_grukt_l + (size_t)n0 * 512, 512,
        2 * UNITS, acc, sm32);

    const int lane = threadIdx.x & 31, warp = threadIdx.x >> 5;
    const int wm = warp / WN, wn = warp % WN;
    const int grp = lane >> 2, qid = lane & 3;
    #pragma unroll
    for (int mt = 0; mt < MT; mt++) {
        int r = m0 + (wm * MT + mt) * 16 + grp;
        #pragma unroll
        for (int nt = 0; nt < NT; nt++) {
            int c = n0 + (wn * NT + nt) * 8 + qid * 2;
            float bb0 = __ldg(&gru_b[c]), bb1 = __ldg(&gru_b[c + 1]);
            g_preact[r * 3 * UNITS + c]           = acc[mt][nt][0] + bb0;
            g_preact[r * 3 * UNITS + c + 1]       = acc[mt][nt][1] + bb1;
            g_preact[(r + 8) * 3 * UNITS + c]     = acc[mt][nt][2] + bb0;
            g_preact[(r + 8) * 3 * UNITS + c + 1] = acc[mt][nt][3] + bb1;
        }
    }
}

// ---------------- kernel 4: GRU gate combine (h == 0) ----------------
__global__ void __launch_bounds__(512) k_gates(const float* __restrict__ gru_b,
                                               float* __restrict__ state) {
    const int b = blockIdx.x, u = threadIdx.x;
    const float* p = g_preact + b * 3 * UNITS;
    const float* gb1 = gru_b + 3 * UNITS;   // gru_b[1]
    float xz = p[u], xr = p[UNITS + u], xh = p[2 * UNITS + u];
    float z = 1.f / (1.f + expf(-(xz + gb1[u])));
    float r = 1.f / (1.f + expf(-(xr + gb1[UNITS + u])));
    float hh = tanhf(xh + r * gb1[2 * UNITS + u]);
    state[b * UNITS + u] = (1.f - z) * hh;   // z*h vanishes (h==0)
}

// ---------------- kernel 5: dense layer (3-pass) ----------------
__global__ void __launch_bounds__(256) k_dense(const float* __restrict__ state,
                                               const float* __restrict__ db) {
    extern __shared__ uint32_t sm32[];
    constexpr int M_BLK = 64, N_BLK = 64, NTHR = 256, WM = 2, WN = 4, MT = 2, NT = 2;
    const int n0 = blockIdx.x * N_BLK;
    const int m0 = blockIdx.y * M_BLK;

    float acc[MT][NT][4] = {};
    gemm_f16<M_BLK, N_BLK, NTHR, WM, WN, MT, NT, 3>(
        state + (size_t)m0 * UNITS, UNITS,
        g_dWt_h + (size_t)n0 * 256, g_dWt_l + (size_t)n0 * 256, 256,
        UNITS, acc, sm32);

    const int lane = threadIdx.x & 31, warp = threadIdx.x >> 5;
    const int wm = warp / WN, wn = warp % WN;
    const int grp = lane >> 2, qid = lane & 3;
    #pragma unroll
    for (int mt = 0; mt < MT; mt++) {
        int r = m0 + (wm * MT + mt) * 16 + grp;
        #pragma unroll
        for (int nt = 0; nt < NT; nt++) {
            int c = n0 + (wn * NT + nt) * 8 + qid * 2;
            float bb0 = __ldg(&db[c]), bb1 = __ldg(&db[c + 1]);
            g_y[r * UNITS + c]           = fmaxf(acc[mt][nt][0] + bb0, 0.f);
            g_y[r * UNITS + c + 1]       = fmaxf(acc[mt][nt][1] + bb1, 0.f);
            g_y[(r + 8) * UNITS + c]     = fmaxf(acc[mt][nt][2] + bb0, 0.f);
            g_y[(r + 8) * UNITS + c + 1] = fmaxf(acc[mt][nt][3] + bb1, 0.f);
        }
    }
}

// ---------------- kernel 6: vocab projection (1-pass, direct oW) ----------------
// logits = y @ oW + ob. Stages oW fp32->fp16 in-kernel: each block owns a
// disjoint 128-col strip, so every oW element is read & converted exactly once.
__global__ void __launch_bounds__(256) k_logits(const float* __restrict__ oW,
                                                const float* __restrict__ ob,
                                                float* __restrict__ logits) {
    extern __shared__ uint32_t sm32[];
    constexpr int M_BLK = 128, N_BLK = 128, NTHR = 256, WM = 4, WN = 2, MT = 2, NT = 8;
    constexpr int P = 20;
    uint32_t* sAh = sm32;
    uint32_t* sBh = sAh + M_BLK * P;

    const int n0 = blockIdx.x * N_BLK;   // 250 blocks
    const int tid = threadIdx.x, lane = tid & 31, warp = tid >> 5;
    const int wm = warp / WN, wn = warp % WN;
    const int grp = lane >> 2, qid = lane & 3;

    float acc[MT][NT][4] = {};
    for (int k0 = 0; k0 < UNITS; k0 += 32) {
        // stage A (y), fp16 hi only
        for (int i = tid; i < M_BLK * 16; i += NTHR) {
            int r = i >> 4, kp = i & 15;
            float2 v = *(const float2*)&g_y[(size_t)r * UNITS + k0 + kp * 2];
            sAh[r * P + kp] = packh(__float2half_rn(v.x), __float2half_rn(v.y));
        }
        // stage B directly from oW fp32 (coalesced over n), convert to fp16
        for (int i = tid; i < N_BLK * 16; i += NTHR) {
            int kp = i >> 7, n = i & 127;
            float v0 = oW[(size_t)(k0 + kp * 2)     * VOCAB + n0 + n];
            float v1 = oW[(size_t)(k0 + kp * 2 + 1) * VOCAB + n0 + n];
            sBh[n * P + kp] = packh(__float2half_rn(v0), __float2half_rn(v1));
        }
        __syncthreads();

        #pragma unroll
        for (int kk = 0; kk < 2; kk++) {
            const int kp0 = kk * 8 + qid;
            uint32_t ah[MT][4];
            #pragma unroll
            for (int mt = 0; mt < MT; mt++) {
                int r = (wm * MT + mt) * 16 + grp;
                ah[mt][0] = sAh[r * P + kp0];
                ah[mt][1] = sAh[(r + 8) * P + kp0];
                ah[mt][2] = sAh[r * P + kp0 + 4];
                ah[mt][3] = sAh[(r + 8) * P + kp0 + 4];
            }
            #pragma unroll
            for (int nt = 0; nt < NT; nt++) {
                int n = (wn * NT + nt) * 8 + grp;
                uint32_t bh0 = sBh[n * P + kp0], bh1 = sBh[n * P + kp0 + 4];
                #pragma unroll
                for (int mt = 0; mt < MT; mt++)
                    mma16(acc[mt][nt], ah[mt], bh0, bh1);
            }
        }
        __syncthreads();
    }

    #pragma unroll
    for (int mt = 0; mt < MT; mt++) {
        int r = (wm * MT + mt) * 16 + grp;
        #pragma unroll
        for (int nt = 0; nt < NT; nt++) {
            int c = n0 + (wn * NT + nt) * 8 + qid * 2;
            float bb0 = __ldg(&ob[c]), bb1 = __ldg(&ob[c + 1]);
            logits[(size_t)r * VOCAB + c]           = acc[mt][nt][0] + bb0;
            logits[(size_t)r * VOCAB + c + 1]       = acc[mt][nt][1] + bb1;
            logits[(size_t)(r + 8) * VOCAB + c]     = acc[mt][nt][2] + bb0;
            logits[(size_t)(r + 8) * VOCAB + c + 1] = acc[mt][nt][3] + bb1;
        }
    }
}

// ---------------- launch ----------------
extern "C" void kernel_launch(void* const* d_in, const int* in_sizes, int n_in,
                              void* d_out, int out_size) {
    const int*   inputs = (const int*)  d_in[0];
    const float* attn   = (const float*)d_in[1];
    const float* W0     = (const float*)d_in[2];
    const float* b0     = (const float*)d_in[3];
    /* d_in[4] = W1   (dead: hidden0 == 0) */
    const float* b1     = (const float*)d_in[5];
    const float* vW     = (const float*)d_in[6];
    /* d_in[7] = vb   (cancels in softmax) */
    const float* emb    = (const float*)d_in[8];
    const float* gru_k  = (const float*)d_in[9];
    /* d_in[10] = gru_rk (dead: h == 0) */
    const float* gru_b  = (const float*)d_in[11];
    const float* dW     = (const float*)d_in[12];
    const float* db     = (const float*)d_in[13];
    const float* oW     = (const float*)d_in[14];
    const float* ob     = (const float*)d_in[15];

    float* out    = (float*)d_out;
    float* logits = out;
    float* state  = out + (size_t)BATCH * VOCAB;
    float* alpha  = state + BATCH * UNITS;

    void *pW0t, *pGkh, *pGkl, *pdWh, *pdWl;
    cudaGetSymbolAddress(&pW0t, g_W0t);
    cudaGetSymbolAddress(&pGkh, g_grukt_h);
    cudaGetSymbolAddress(&pGkl, g_grukt_l);
    cudaGetSymbolAddress(&pdWh, g_dWt_h);
    cudaGetSymbolAddress(&pdWl, g_dWt_l);

    // small-weight pre-split (deterministic; runs each replay)
    k_conv<<<dim3(8,   8), 256>>>(W0,    (uint32_t*)pW0t, nullptr,          512,  512);
    k_conv<<<dim3(24, 16), 256>>>(gru_k, (uint32_t*)pGkh, (uint32_t*)pGkl, 1024, 1536);
    k_conv<<<dim3(8,   8), 256>>>(dW,    (uint32_t*)pdWh, (uint32_t*)pdWl,  512,  512);

    // dynamic smem (bytes)
    const int SM_SCORE  = ((64 + 128) * 20 + SEQ) * 4;     // 15616
    const int SM_SMALL  = (64 * 40 + 64 * 40) * 4;         // 20480
    const int SM_LOGITS = ((128 + 128) * 20) * 4;          // 20480

    k_score<<<BATCH, 512, SM_SCORE>>>(attn, b0, b1, vW);
    k_softmax_ctx<<<BATCH, 256>>>(attn, inputs, emb, alpha);
    k_gru<<<dim3(24, 2), 256, SM_SMALL>>>(gru_b);
    k_gates<<<BATCH, UNITS>>>(gru_b, state);
    k_dense<<<dim3(8, 2), 256, SM_SMALL>>>(state, db);
    k_logits<<<250, 256, SM_LOGITS>>>(oW, ob, logits);
}